// round 1
// baseline (speedup 1.0000x reference)
#include <cuda_runtime.h>

// ---------------- problem constants ----------------
#define B   512
#define NN  21
#define II  256
#define HH  1024
#define FH  4096          // 4*HH
#define KK  1280          // II + HH
#define EPS 1e-12f

// ---------------- scratch (allocation-free: __device__ globals) ----------------
__device__ float g_gates[(size_t)B * NN * FH];   // [B][NN][4H] pre-mix gates
__device__ float g_gx[NN * NN];                  // row-L1-normalized G

// ---------------- packed f32x2 helpers ----------------
__device__ __forceinline__ void ffma2(unsigned long long &d,
                                      unsigned long long a,
                                      unsigned long long b) {
    asm("fma.rn.f32x2 %0, %1, %2, %0;" : "+l"(d) : "l"(a), "l"(b));
}
__device__ __forceinline__ unsigned long long pk(float x, float y) {
    unsigned long long r;
    asm("mov.b64 %0, {%1, %2};" : "=l"(r) : "f"(x), "f"(y));
    return r;
}
__device__ __forceinline__ float2 upk(unsigned long long v) {
    float2 r;
    asm("mov.b64 {%0, %1}, %2;" : "=f"(r.x), "=f"(r.y) : "l"(v));
    return r;
}

// ---------------- kernel 0: gx = L1-row-normalize(G); gx_out = normalize(gx) ----------------
__global__ void gx_kernel(const float* __restrict__ G, float* __restrict__ gx_out) {
    __shared__ float sG[NN * NN];
    __shared__ float den[NN];
    __shared__ float den2[NN];
    int tid = threadIdx.x;

    for (int i = tid; i < NN * NN; i += blockDim.x) sG[i] = G[i];
    __syncthreads();
    if (tid < NN) {
        float s = 0.f;
        for (int j = 0; j < NN; j++) s += fabsf(sG[tid * NN + j]);
        den[tid] = fmaxf(s, EPS);
    }
    __syncthreads();
    for (int i = tid; i < NN * NN; i += blockDim.x) sG[i] = sG[i] / den[i / NN];
    __syncthreads();
    if (tid < NN) {
        float s = 0.f;
        for (int j = 0; j < NN; j++) s += fabsf(sG[tid * NN + j]);
        den2[tid] = fmaxf(s, EPS);
    }
    __syncthreads();
    for (int i = tid; i < NN * NN; i += blockDim.x) {
        g_gx[i]   = sG[i];
        gx_out[i] = sG[i] / den2[i / NN];
    }
}

// ---------------- kernel 1: gates[b][n][o] = [x|h] @ [Wih|Whh]^T + b_hh ----------------
// Tiles: TM=128 (batch) x TN=64 (out) x TK=16, 256 threads, 8x4 per thread via f32x2.
#define TM 128
#define TN 64
#define TK 16

__global__ __launch_bounds__(256)
void gates_gemm(const float* __restrict__ input, const float* __restrict__ hx,
                const float* __restrict__ Wih,   const float* __restrict__ Whh,
                const float* __restrict__ bhh,   const int* __restrict__ ntypes) {
    __shared__ __align__(16) float As[TK][TM];
    __shared__ __align__(16) float Bs[TK][TN];

    const int n  = blockIdx.z;
    const int bm = blockIdx.y * TM;
    const int bo = blockIdx.x * TN;
    const int nt = ntypes[n];
    const int tid = threadIdx.x;

    const float* wih = Wih + (size_t)nt * FH * II;
    const float* whh = Whh + (size_t)nt * FH * HH;

    // packed accumulators: acc[ip][j] holds rows (2ip, 2ip+1) of col j
    unsigned long long acc[4][4];
#pragma unroll
    for (int i = 0; i < 4; i++)
#pragma unroll
        for (int j = 0; j < 4; j++) acc[i][j] = 0ULL;  // {+0.f, +0.f}

    const int ty = tid >> 4;   // 0..15 -> m block of 8
    const int tx = tid & 15;   // 0..15 -> o block of 4

#pragma unroll 1
    for (int kt = 0; kt < KK / TK; ++kt) {
        const int k0 = kt * TK;

        // load A tile: 128 x 16, two float4 per thread
#pragma unroll
        for (int i = 0; i < 2; i++) {
            int f  = tid + i * 256;
            int m  = f >> 2;
            int k4 = f & 3;
            int b  = bm + m;
            int k  = k0 + k4 * 4;
            const float* src = (k < II)
                ? input + (size_t)b * (NN * II) + (size_t)n * II + k
                : hx    + (size_t)b * (NN * HH) + (size_t)n * HH + (k - II);
            float4 v = *(const float4*)src;
            As[k4 * 4 + 0][m] = v.x;
            As[k4 * 4 + 1][m] = v.y;
            As[k4 * 4 + 2][m] = v.z;
            As[k4 * 4 + 3][m] = v.w;
        }
        // load B tile: 64 x 16, one float4 per thread
        {
            int f  = tid;
            int nn = f >> 2;
            int k4 = f & 3;
            int o  = bo + nn;
            int k  = k0 + k4 * 4;
            const float* src = (k < II)
                ? wih + (size_t)o * II + k
                : whh + (size_t)o * HH + (k - II);
            float4 v = *(const float4*)src;
            Bs[k4 * 4 + 0][nn] = v.x;
            Bs[k4 * 4 + 1][nn] = v.y;
            Bs[k4 * 4 + 2][nn] = v.z;
            Bs[k4 * 4 + 3][nn] = v.w;
        }
        __syncthreads();

#pragma unroll
        for (int k = 0; k < TK; k++) {
            float4 a0 = *(const float4*)&As[k][ty * 8];
            float4 a1 = *(const float4*)&As[k][ty * 8 + 4];
            float4 bv = *(const float4*)&Bs[k][tx * 4];
            unsigned long long ap[4];
            ap[0] = pk(a0.x, a0.y);
            ap[1] = pk(a0.z, a0.w);
            ap[2] = pk(a1.x, a1.y);
            ap[3] = pk(a1.z, a1.w);
            unsigned long long bd[4];
            bd[0] = pk(bv.x, bv.x);
            bd[1] = pk(bv.y, bv.y);
            bd[2] = pk(bv.z, bv.z);
            bd[3] = pk(bv.w, bv.w);
#pragma unroll
            for (int ip = 0; ip < 4; ip++)
#pragma unroll
                for (int j = 0; j < 4; j++) ffma2(acc[ip][j], ap[ip], bd[j]);
        }
        __syncthreads();
    }

    // epilogue: add bias, store float4 rows
    float4 bias = *(const float4*)(bhh + (size_t)nt * FH + bo + tx * 4);
#pragma unroll
    for (int ip = 0; ip < 4; ip++) {
        float2 p0 = upk(acc[ip][0]);
        float2 p1 = upk(acc[ip][1]);
        float2 p2 = upk(acc[ip][2]);
        float2 p3 = upk(acc[ip][3]);
        int m0 = bm + ty * 8 + ip * 2;
        float4 r0 = make_float4(p0.x + bias.x, p1.x + bias.y, p2.x + bias.z, p3.x + bias.w);
        float4 r1 = make_float4(p0.y + bias.x, p1.y + bias.y, p2.y + bias.z, p3.y + bias.w);
        *(float4*)&g_gates[((size_t)m0       * NN + n) * FH + bo + tx * 4] = r0;
        *(float4*)&g_gates[((size_t)(m0 + 1) * NN + n) * FH + bo + tx * 4] = r1;
    }
}

// ---------------- kernel 2: graph mix over n + LSTM epilogue ----------------
__global__ __launch_bounds__(128)
void pass2(const float* __restrict__ cx, const int* __restrict__ tptr,
           float* __restrict__ hy, float* __restrict__ cyo) {
    __shared__ float sgx[NN * NN];
    const int tid = threadIdx.x;
    for (int i = tid; i < NN * NN; i += 128) sgx[i] = g_gx[i];
    __syncthreads();

    const int b = blockIdx.y;
    const int h = blockIdx.x * 128 + tid;

    const float t1    = (float)(*tptr) + 1.0f;
    const float phase = floorf((float)h / (float)(HH - 1) * 8.0f + 1.0f);
    const float mask  = (fmodf(t1, phase) < 0.01f) ? 1.0f : 0.0f;

    // keep all 21 nodes x 4 gates in registers (coalesced global loads)
    float rg0[NN], rg1[NN], rg2[NN], rg3[NN];
    const float* gbase = g_gates + (size_t)b * NN * FH + h;
#pragma unroll
    for (int n = 0; n < NN; n++) {
        rg0[n] = gbase[(size_t)n * FH];
        rg1[n] = gbase[(size_t)n * FH + HH];
        rg2[n] = gbase[(size_t)n * FH + 2 * HH];
        rg3[n] = gbase[(size_t)n * FH + 3 * HH];
    }

#pragma unroll 1
    for (int m = 0; m < NN; m++) {
        float ig = 0.f, fg = 0.f, cg = 0.f, og = 0.f;
#pragma unroll
        for (int n = 0; n < NN; n++) {
            float w = sgx[m * NN + n];
            ig = fmaf(w, rg0[n], ig);
            fg = fmaf(w, rg1[n], fg);
            cg = fmaf(w, rg2[n], cg);
            og = fmaf(w, rg3[n], og);
        }
        float is = 1.f / (1.f + expf(-ig));
        float fs = 1.f / (1.f + expf(-fg));
        float ct = tanhf(cg);
        float os = 1.f / (1.f + expf(-og));

        size_t idx = ((size_t)b * NN + m) * HH + h;
        float cxv = cx[idx];
        float cyv = mask * (fs * cxv + is * ct) + (1.0f - mask) * cxv;
        float hyv = os * tanhf(cyv);
        hy[idx]  = hyv;
        cyo[idx] = cyv;
    }
}

// ---------------- launch ----------------
extern "C" void kernel_launch(void* const* d_in, const int* in_sizes, int n_in,
                              void* d_out, int out_size) {
    const float* input  = (const float*)d_in[0];
    const float* hx     = (const float*)d_in[1];
    const float* cx     = (const float*)d_in[2];
    const float* G      = (const float*)d_in[3];
    const float* wih    = (const float*)d_in[4];
    const float* whh    = (const float*)d_in[5];
    const float* bhh    = (const float*)d_in[6];
    const int*   ntypes = (const int*)d_in[7];
    const int*   tptr   = (const int*)d_in[8];

    float* hy   = (float*)d_out;
    float* cy   = hy + (size_t)B * NN * HH;
    float* gxo  = cy + (size_t)B * NN * HH;

    gx_kernel<<<1, 512>>>(G, gxo);

    dim3 grid1(FH / TN, B / TM, NN);   // (64, 4, 21)
    gates_gemm<<<grid1, 256>>>(input, hx, wih, whh, bhh, ntypes);

    dim3 grid2(HH / 128, B);           // (8, 512)
    pass2<<<grid2, 128>>>(cx, tptr, hy, cy);
}

// round 3
// speedup vs baseline: 2.9551x; 2.9551x over previous
#include <cuda_runtime.h>
#include <cstdint>

// ---------------- problem constants ----------------
#define B   512
#define NN  21
#define II  256
#define HH  1024
#define FH  4096          // 4*HH
#define KK  1280          // II + HH
#define EPS 1e-12f

// ---------------- GEMM tiling ----------------
#define TM 128            // batch rows per CTA
#define TN 256            // out cols per CTA
#define TK 32             // K floats per stage
#define NSTAGE 3
#define NCHUNK (KK / TK)  // 40
#define PADK 36           // floats per smem row (32 + 4 pad, keeps 16B align)

#define A_STAGE (TM * PADK)        // floats
#define B_STAGE (TN * PADK)
#define SM_FLOATS (NSTAGE * (A_STAGE + B_STAGE))
#define SM_BYTES  (SM_FLOATS * 4)  // 165888

// ---------------- scratch ----------------
__device__ float g_gates[(size_t)B * NN * FH];   // [B][NN][4H] pre-mix gates
__device__ float g_gx[NN * NN];                  // row-L1-normalized G

// ---------------- helpers ----------------
__device__ __forceinline__ uint32_t smem_u32(const void* p) {
    uint32_t a;
    asm("{ .reg .u64 t; cvta.to.shared.u64 t, %1; cvt.u32.u64 %0, t; }" : "=r"(a) : "l"(p));
    return a;
}
__device__ __forceinline__ void cp16(uint32_t saddr, const void* gptr) {
    asm volatile("cp.async.cg.shared.global [%0], [%1], 16;" :: "r"(saddr), "l"(gptr));
}
__device__ __forceinline__ uint32_t f2tf(float x) {
    uint32_t r;
    asm("cvt.rna.tf32.f32 %0, %1;" : "=r"(r) : "f"(x));
    return r;
}
__device__ __forceinline__ void mma8(float* c, const uint32_t* a, const uint32_t* b) {
    asm volatile(
        "mma.sync.aligned.m16n8k8.row.col.f32.tf32.tf32.f32 "
        "{%0,%1,%2,%3}, {%4,%5,%6,%7}, {%8,%9}, {%0,%1,%2,%3};"
        : "+f"(c[0]), "+f"(c[1]), "+f"(c[2]), "+f"(c[3])
        : "r"(a[0]), "r"(a[1]), "r"(a[2]), "r"(a[3]), "r"(b[0]), "r"(b[1]));
}

// ---------------- kernel 0: gx normalization ----------------
__global__ void gx_kernel(const float* __restrict__ G, float* __restrict__ gx_out) {
    __shared__ float sG[NN * NN];
    __shared__ float den[NN];
    __shared__ float den2[NN];
    int tid = threadIdx.x;
    for (int i = tid; i < NN * NN; i += blockDim.x) sG[i] = G[i];
    __syncthreads();
    if (tid < NN) {
        float s = 0.f;
        for (int j = 0; j < NN; j++) s += fabsf(sG[tid * NN + j]);
        den[tid] = fmaxf(s, EPS);
    }
    __syncthreads();
    for (int i = tid; i < NN * NN; i += blockDim.x) sG[i] = sG[i] / den[i / NN];
    __syncthreads();
    if (tid < NN) {
        float s = 0.f;
        for (int j = 0; j < NN; j++) s += fabsf(sG[tid * NN + j]);
        den2[tid] = fmaxf(s, EPS);
    }
    __syncthreads();
    for (int i = tid; i < NN * NN; i += blockDim.x) {
        g_gx[i]   = sG[i];
        gx_out[i] = sG[i] / den2[i / NN];
    }
}

// ---------------- kernel 1: tf32 mma.sync gates GEMM ----------------
// g_gates[b][n][o] = [input|hx] @ [Wih|Whh]^T + bias
__global__ __launch_bounds__(256, 1)
void gates_gemm(const float* __restrict__ input, const float* __restrict__ hx,
                const float* __restrict__ Wih,   const float* __restrict__ Whh,
                const float* __restrict__ bhh,   const int* __restrict__ ntypes) {
    extern __shared__ float smf[];
    const int tid  = threadIdx.x;
    const int lane = tid & 31;
    const int wid  = tid >> 5;

    const int n  = blockIdx.z;
    const int bm = blockIdx.y * TM;
    const int bo = blockIdx.x * TN;
    const int nt = ntypes[n];
    const float* wih = Wih + (size_t)nt * FH * II;
    const float* whh = Whh + (size_t)nt * FH * HH;

    const uint32_t sb = smem_u32(smf);

    // warp tiling: 2 (m) x 4 (n), warp tile 64x64
    const int wm = (wid & 1) * 64;
    const int wn = (wid >> 1) * 64;
    const int lr = lane >> 2;   // 0..7
    const int lq = lane & 3;    // 0..3

    float acc[4][8][4];
#pragma unroll
    for (int i = 0; i < 4; i++)
#pragma unroll
        for (int j = 0; j < 8; j++)
#pragma unroll
            for (int v = 0; v < 4; v++) acc[i][j][v] = 0.f;

    // ---- stage loader ----
    auto load_stage = [&](int kt) {
        const int s  = kt % NSTAGE;
        const int k0 = kt * TK;
        const uint32_t ab = sb + (uint32_t)(s * (A_STAGE + B_STAGE)) * 4u;
        const uint32_t bb = ab + (uint32_t)A_STAGE * 4u;
        // A: 128 rows x 8 chunks = 1024 / 256 threads = 4
#pragma unroll
        for (int i = 0; i < 4; i++) {
            int f = tid + i * 256;
            int r = f >> 3, c = f & 7;
            int k = k0 + c * 4;
            const float* src = (k < II)
                ? input + ((size_t)(bm + r) * NN + n) * II + k
                : hx    + ((size_t)(bm + r) * NN + n) * HH + (k - II);
            cp16(ab + (uint32_t)(r * PADK + c * 4) * 4u, src);
        }
        // B: 256 rows x 8 chunks = 2048 / 256 = 8
#pragma unroll
        for (int i = 0; i < 8; i++) {
            int f = tid + i * 256;
            int r = f >> 3, c = f & 7;
            int k = k0 + c * 4;
            const float* src = (k < II)
                ? wih + (size_t)(bo + r) * II + k
                : whh + (size_t)(bo + r) * HH + (k - II);
            cp16(bb + (uint32_t)(r * PADK + c * 4) * 4u, src);
        }
    };

    // prologue
#pragma unroll
    for (int s = 0; s < NSTAGE; s++) {
        load_stage(s);
        asm volatile("cp.async.commit_group;" ::: "memory");
    }

    // mainloop
    for (int kt = 0; kt < NCHUNK; kt++) {
        asm volatile("cp.async.wait_group 2;" ::: "memory");
        __syncthreads();

        const int s = kt % NSTAGE;
        const float* sA = smf + s * (A_STAGE + B_STAGE);
        const float* sB = sA + A_STAGE;

#pragma unroll
        for (int ks = 0; ks < TK / 8; ks++) {
            const int k0 = ks * 8;
            uint32_t af[4][4];
#pragma unroll
            for (int mi = 0; mi < 4; mi++) {
                const float* ar = sA + (wm + mi * 16 + lr) * PADK + k0 + lq;
                af[mi][0] = f2tf(ar[0]);
                af[mi][1] = f2tf(ar[8 * PADK]);
                af[mi][2] = f2tf(ar[4]);
                af[mi][3] = f2tf(ar[8 * PADK + 4]);
            }
            uint32_t bf[8][2];
#pragma unroll
            for (int ni = 0; ni < 8; ni++) {
                const float* br = sB + (wn + ni * 8 + lr) * PADK + k0 + lq;
                bf[ni][0] = f2tf(br[0]);
                bf[ni][1] = f2tf(br[4]);
            }
#pragma unroll
            for (int mi = 0; mi < 4; mi++)
#pragma unroll
                for (int ni = 0; ni < 8; ni++) mma8(acc[mi][ni], af[mi], bf[ni]);
        }
        __syncthreads();
        if (kt + NSTAGE < NCHUNK) load_stage(kt + NSTAGE);
        asm volatile("cp.async.commit_group;" ::: "memory");
    }

    // ---- epilogue: bias + store ----
    const float* brow = bhh + (size_t)nt * FH + bo;
#pragma unroll
    for (int mi = 0; mi < 4; mi++) {
        int r0 = wm + mi * 16 + lr;        // local row of c0/c1
        float* out0 = g_gates + ((size_t)(bm + r0)     * NN + n) * FH + bo;
        float* out1 = g_gates + ((size_t)(bm + r0 + 8) * NN + n) * FH + bo;
#pragma unroll
        for (int ni = 0; ni < 8; ni++) {
            int col = wn + ni * 8 + lq * 2;
            float2 bv = *(const float2*)(brow + col);
            float2 v0 = make_float2(acc[mi][ni][0] + bv.x, acc[mi][ni][1] + bv.y);
            float2 v1 = make_float2(acc[mi][ni][2] + bv.x, acc[mi][ni][3] + bv.y);
            *(float2*)(out0 + col) = v0;
            *(float2*)(out1 + col) = v1;
        }
    }
}

// ---------------- kernel 2: graph mix over n + LSTM epilogue ----------------
__global__ __launch_bounds__(128)
void pass2(const float* __restrict__ cx, const int* __restrict__ tptr,
           float* __restrict__ hy, float* __restrict__ cyo) {
    __shared__ float sgx[NN * NN];
    const int tid = threadIdx.x;
    for (int i = tid; i < NN * NN; i += 128) sgx[i] = g_gx[i];
    __syncthreads();

    const int b = blockIdx.y;
    const int h = blockIdx.x * 128 + tid;

    const float t1    = (float)(*tptr) + 1.0f;
    const float phase = floorf((float)h / (float)(HH - 1) * 8.0f + 1.0f);
    const float mask  = (fmodf(t1, phase) < 0.01f) ? 1.0f : 0.0f;

    float rg0[NN], rg1[NN], rg2[NN], rg3[NN];
    const float* gbase = g_gates + (size_t)b * NN * FH + h;
#pragma unroll
    for (int nI = 0; nI < NN; nI++) {
        rg0[nI] = gbase[(size_t)nI * FH];
        rg1[nI] = gbase[(size_t)nI * FH + HH];
        rg2[nI] = gbase[(size_t)nI * FH + 2 * HH];
        rg3[nI] = gbase[(size_t)nI * FH + 3 * HH];
    }

#pragma unroll 1
    for (int m = 0; m < NN; m++) {
        float ig = 0.f, fg = 0.f, cg = 0.f, og = 0.f;
#pragma unroll
        for (int nI = 0; nI < NN; nI++) {
            float w = sgx[m * NN + nI];
            ig = fmaf(w, rg0[nI], ig);
            fg = fmaf(w, rg1[nI], fg);
            cg = fmaf(w, rg2[nI], cg);
            og = fmaf(w, rg3[nI], og);
        }
        float is = 1.f / (1.f + expf(-ig));
        float fs = 1.f / (1.f + expf(-fg));
        float ct = tanhf(cg);
        float os = 1.f / (1.f + expf(-og));

        size_t idx = ((size_t)b * NN + m) * HH + h;
        float cxv = cx[idx];
        float cyv = mask * (fs * cxv + is * ct) + (1.0f - mask) * cxv;
        float hyv = os * tanhf(cyv);
        hy[idx]  = hyv;
        cyo[idx] = cyv;
    }
}

// ---------------- launch ----------------
extern "C" void kernel_launch(void* const* d_in, const int* in_sizes, int n_in,
                              void* d_out, int out_size) {
    const float* input  = (const float*)d_in[0];
    const float* hx     = (const float*)d_in[1];
    const float* cx     = (const float*)d_in[2];
    const float* G      = (const float*)d_in[3];
    const float* wih    = (const float*)d_in[4];
    const float* whh    = (const float*)d_in[5];
    const float* bhh    = (const float*)d_in[6];
    const int*   ntypes = (const int*)d_in[7];
    const int*   tptr   = (const int*)d_in[8];

    float* hy  = (float*)d_out;
    float* cy  = hy + (size_t)B * NN * HH;
    float* gxo = cy + (size_t)B * NN * HH;

    cudaFuncSetAttribute(gates_gemm, cudaFuncAttributeMaxDynamicSharedMemorySize, SM_BYTES);

    gx_kernel<<<1, 512>>>(G, gxo);

    dim3 grid1(FH / TN, B / TM, NN);   // (16, 4, 21)
    gates_gemm<<<grid1, 256, SM_BYTES>>>(input, hx, wih, whh, bhh, ntypes);

    dim3 grid2(HH / 128, B);           // (8, 512)
    pass2<<<grid2, 128>>>(cx, tptr, hy, cy);
}

// round 4
// speedup vs baseline: 3.0313x; 1.0258x over previous
#include <cuda_runtime.h>
#include <cstdint>

// ---------------- problem constants ----------------
#define B   512
#define NN  21
#define II  256
#define HH  1024
#define FH  4096          // 4*HH
#define KK  1280          // II + HH
#define EPS 1e-12f

// ---------------- GEMM tiling ----------------
#define TM 128            // batch rows per CTA
#define TN 256            // out cols per CTA
#define TK 32             // K floats per stage
#define NSTAGE 3
#define NCHUNK (KK / TK)  // 40
#define PADK 36           // floats per smem row (32 + 4 pad; keeps 16B align, LDSM conflict-free)

#define A_STAGE (TM * PADK)        // floats
#define B_STAGE (TN * PADK)
#define SM_FLOATS (NSTAGE * (A_STAGE + B_STAGE))
#define SM_BYTES  (SM_FLOATS * 4)  // 165888

// ---------------- scratch (__device__ globals; no allocation) ----------------
__device__ float g_gates[(size_t)B * NN * FH];     // [B][NN][4H] pre-mix gates
__device__ float g_gx[NN * NN];                    // row-L1-normalized G
__device__ float g_wih_t[(size_t)5 * FH * II];     // tf32-rounded weights
__device__ float g_whh_t[(size_t)5 * FH * HH];
__device__ float g_in_t[(size_t)B * NN * II];      // tf32-rounded input
__device__ float g_hx_t[(size_t)B * NN * HH];      // tf32-rounded hx

// ---------------- helpers ----------------
__device__ __forceinline__ uint32_t smem_u32(const void* p) {
    uint32_t a;
    asm("{ .reg .u64 t; cvta.to.shared.u64 t, %1; cvt.u32.u64 %0, t; }" : "=r"(a) : "l"(p));
    return a;
}
__device__ __forceinline__ void cp16(uint32_t saddr, const void* gptr) {
    asm volatile("cp.async.cg.shared.global [%0], [%1], 16;" :: "r"(saddr), "l"(gptr));
}
__device__ __forceinline__ float f2tf_f(float x) {
    uint32_t r;
    asm("cvt.rna.tf32.f32 %0, %1;" : "=r"(r) : "f"(x));
    return __uint_as_float(r);
}
__device__ __forceinline__ void ldsm4(uint32_t* r, uint32_t saddr) {
    asm volatile("ldmatrix.sync.aligned.m8n8.x4.shared.b16 {%0,%1,%2,%3}, [%4];"
                 : "=r"(r[0]), "=r"(r[1]), "=r"(r[2]), "=r"(r[3]) : "r"(saddr));
}
__device__ __forceinline__ void mma8(float* c, const uint32_t* a, const uint32_t* b) {
    asm volatile(
        "mma.sync.aligned.m16n8k8.row.col.f32.tf32.tf32.f32 "
        "{%0,%1,%2,%3}, {%4,%5,%6,%7}, {%8,%9}, {%0,%1,%2,%3};"
        : "+f"(c[0]), "+f"(c[1]), "+f"(c[2]), "+f"(c[3])
        : "r"(a[0]), "r"(a[1]), "r"(a[2]), "r"(a[3]), "r"(b[0]), "r"(b[1]));
}

// ---------------- kernel: elementwise tf32 rounding (float4 grid-stride) ----------------
__global__ void cvt_kernel(const float4* __restrict__ src, float4* __restrict__ dst, int n4) {
    int i = blockIdx.x * blockDim.x + threadIdx.x;
    if (i < n4) {
        float4 v = src[i];
        v.x = f2tf_f(v.x); v.y = f2tf_f(v.y); v.z = f2tf_f(v.z); v.w = f2tf_f(v.w);
        dst[i] = v;
    }
}

// ---------------- kernel 0: gx normalization ----------------
__global__ void gx_kernel(const float* __restrict__ G, float* __restrict__ gx_out) {
    __shared__ float sG[NN * NN];
    __shared__ float den[NN];
    __shared__ float den2[NN];
    int tid = threadIdx.x;
    for (int i = tid; i < NN * NN; i += blockDim.x) sG[i] = G[i];
    __syncthreads();
    if (tid < NN) {
        float s = 0.f;
        for (int j = 0; j < NN; j++) s += fabsf(sG[tid * NN + j]);
        den[tid] = fmaxf(s, EPS);
    }
    __syncthreads();
    for (int i = tid; i < NN * NN; i += blockDim.x) sG[i] = sG[i] / den[i / NN];
    __syncthreads();
    if (tid < NN) {
        float s = 0.f;
        for (int j = 0; j < NN; j++) s += fabsf(sG[tid * NN + j]);
        den2[tid] = fmaxf(s, EPS);
    }
    __syncthreads();
    for (int i = tid; i < NN * NN; i += blockDim.x) {
        g_gx[i]   = sG[i];
        gx_out[i] = sG[i] / den2[i / NN];
    }
}

// ---------------- kernel 1: tf32 mma.sync gates GEMM (ldmatrix fragments) ----------------
__global__ __launch_bounds__(256, 1)
void gates_gemm(const float* __restrict__ bhh, const int* __restrict__ ntypes) {
    extern __shared__ float smf[];
    const int tid  = threadIdx.x;
    const int lane = tid & 31;
    const int wid  = tid >> 5;

    const int n  = blockIdx.z;
    const int bm = blockIdx.y * TM;
    const int bo = blockIdx.x * TN;
    const int nt = ntypes[n];
    const float* wih = g_wih_t + (size_t)nt * FH * II;
    const float* whh = g_whh_t + (size_t)nt * FH * HH;

    const uint32_t sb = smem_u32(smf);

    // warp tiling: 2 (m) x 4 (n), warp tile 64x64
    const int wm = (wid & 1) * 64;
    const int wn = (wid >> 1) * 64;

    // ldmatrix lane roles
    // A (one mi = 16 rows x 8 k): mat = lane>>3; row = (mat&1)*8 + lane&7; koff = (mat>>1)*4
    const int a_row  = ((lane >> 3) & 1) * 8 + (lane & 7);
    const int a_koff = (lane >> 4) * 4;
    // B (one np = two ni = 16 n-rows x 8 k): row = (lane>>4)*8 + lane&7; koff = ((lane>>3)&1)*4
    const int b_row  = (lane >> 4) * 8 + (lane & 7);
    const int b_koff = ((lane >> 3) & 1) * 4;

    float acc[4][8][4];
#pragma unroll
    for (int i = 0; i < 4; i++)
#pragma unroll
        for (int j = 0; j < 8; j++)
#pragma unroll
            for (int v = 0; v < 4; v++) acc[i][j][v] = 0.f;

    // ---- stage loader ----
    auto load_stage = [&](int kt) {
        const int s  = kt % NSTAGE;
        const int k0 = kt * TK;
        const uint32_t ab = sb + (uint32_t)(s * (A_STAGE + B_STAGE)) * 4u;
        const uint32_t bb = ab + (uint32_t)A_STAGE * 4u;
#pragma unroll
        for (int i = 0; i < 4; i++) {
            int f = tid + i * 256;
            int r = f >> 3, c = f & 7;
            int k = k0 + c * 4;
            const float* src = (k < II)
                ? g_in_t + ((size_t)(bm + r) * NN + n) * II + k
                : g_hx_t + ((size_t)(bm + r) * NN + n) * HH + (k - II);
            cp16(ab + (uint32_t)(r * PADK + c * 4) * 4u, src);
        }
#pragma unroll
        for (int i = 0; i < 8; i++) {
            int f = tid + i * 256;
            int r = f >> 3, c = f & 7;
            int k = k0 + c * 4;
            const float* src = (k < II)
                ? wih + (size_t)(bo + r) * II + k
                : whh + (size_t)(bo + r) * HH + (k - II);
            cp16(bb + (uint32_t)(r * PADK + c * 4) * 4u, src);
        }
    };

    // prologue
#pragma unroll
    for (int s = 0; s < NSTAGE; s++) {
        load_stage(s);
        asm volatile("cp.async.commit_group;" ::: "memory");
    }

    // mainloop
    for (int kt = 0; kt < NCHUNK; kt++) {
        asm volatile("cp.async.wait_group 2;" ::: "memory");
        __syncthreads();

        const int s = kt % NSTAGE;
        const uint32_t sAb = sb + (uint32_t)(s * (A_STAGE + B_STAGE)) * 4u;
        const uint32_t sBb = sAb + (uint32_t)A_STAGE * 4u;

        // per-lane fixed byte offsets
        const uint32_t aL = (uint32_t)(a_row * PADK + a_koff) * 4u;
        const uint32_t bL = (uint32_t)(b_row * PADK + b_koff) * 4u;

#pragma unroll
        for (int ks = 0; ks < TK / 8; ks++) {
            const uint32_t kb = (uint32_t)(ks * 8) * 4u;
            uint32_t af[4][4];
#pragma unroll
            for (int mi = 0; mi < 4; mi++)
                ldsm4(af[mi], sAb + (uint32_t)((wm + mi * 16) * PADK) * 4u + kb + aL);
            uint32_t bq[4][4];
#pragma unroll
            for (int np = 0; np < 4; np++)
                ldsm4(bq[np], sBb + (uint32_t)((wn + np * 16) * PADK) * 4u + kb + bL);
#pragma unroll
            for (int mi = 0; mi < 4; mi++)
#pragma unroll
                for (int ni = 0; ni < 8; ni++)
                    mma8(acc[mi][ni], af[mi], &bq[ni >> 1][(ni & 1) * 2]);
        }
        __syncthreads();
        if (kt + NSTAGE < NCHUNK) load_stage(kt + NSTAGE);
        asm volatile("cp.async.commit_group;" ::: "memory");
    }

    // ---- epilogue: bias + store (verified mapping from round 3) ----
    const int lr = lane >> 2;
    const int lq = lane & 3;
    const float* brow = bhh + (size_t)nt * FH + bo;
#pragma unroll
    for (int mi = 0; mi < 4; mi++) {
        int r0 = wm + mi * 16 + lr;
        float* out0 = g_gates + ((size_t)(bm + r0)     * NN + n) * FH + bo;
        float* out1 = g_gates + ((size_t)(bm + r0 + 8) * NN + n) * FH + bo;
#pragma unroll
        for (int ni = 0; ni < 8; ni++) {
            int col = wn + ni * 8 + lq * 2;
            float2 bv = *(const float2*)(brow + col);
            float2 v0 = make_float2(acc[mi][ni][0] + bv.x, acc[mi][ni][1] + bv.y);
            float2 v1 = make_float2(acc[mi][ni][2] + bv.x, acc[mi][ni][3] + bv.y);
            *(float2*)(out0 + col) = v0;
            *(float2*)(out1 + col) = v1;
        }
    }
}

// ---------------- kernel 2: graph mix over n + LSTM epilogue ----------------
__global__ __launch_bounds__(128)
void pass2(const float* __restrict__ cx, const int* __restrict__ tptr,
           float* __restrict__ hy, float* __restrict__ cyo) {
    __shared__ float sgx[NN * NN];
    const int tid = threadIdx.x;
    for (int i = tid; i < NN * NN; i += 128) sgx[i] = g_gx[i];
    __syncthreads();

    const int b = blockIdx.y;
    const int h = blockIdx.x * 128 + tid;

    const float t1    = (float)(*tptr) + 1.0f;
    const float phase = floorf((float)h / (float)(HH - 1) * 8.0f + 1.0f);
    const float mask  = (fmodf(t1, phase) < 0.01f) ? 1.0f : 0.0f;

    float rg0[NN], rg1[NN], rg2[NN], rg3[NN];
    const float* gbase = g_gates + (size_t)b * NN * FH + h;
#pragma unroll
    for (int nI = 0; nI < NN; nI++) {
        rg0[nI] = gbase[(size_t)nI * FH];
        rg1[nI] = gbase[(size_t)nI * FH + HH];
        rg2[nI] = gbase[(size_t)nI * FH + 2 * HH];
        rg3[nI] = gbase[(size_t)nI * FH + 3 * HH];
    }

#pragma unroll 1
    for (int m = 0; m < NN; m++) {
        float ig = 0.f, fg = 0.f, cg = 0.f, og = 0.f;
#pragma unroll
        for (int nI = 0; nI < NN; nI++) {
            float w = sgx[m * NN + nI];
            ig = fmaf(w, rg0[nI], ig);
            fg = fmaf(w, rg1[nI], fg);
            cg = fmaf(w, rg2[nI], cg);
            og = fmaf(w, rg3[nI], og);
        }
        float is = 1.f / (1.f + expf(-ig));
        float fs = 1.f / (1.f + expf(-fg));
        float ct = tanhf(cg);
        float os = 1.f / (1.f + expf(-og));

        size_t idx = ((size_t)b * NN + m) * HH + h;
        float cxv = cx[idx];
        float cyv = mask * (fs * cxv + is * ct) + (1.0f - mask) * cxv;
        float hyv = os * tanhf(cyv);
        hy[idx]  = hyv;
        cyo[idx] = cyv;
    }
}

// ---------------- launch ----------------
extern "C" void kernel_launch(void* const* d_in, const int* in_sizes, int n_in,
                              void* d_out, int out_size) {
    const float* input  = (const float*)d_in[0];
    const float* hx     = (const float*)d_in[1];
    const float* cx     = (const float*)d_in[2];
    const float* G      = (const float*)d_in[3];
    const float* wih    = (const float*)d_in[4];
    const float* whh    = (const float*)d_in[5];
    const float* bhh    = (const float*)d_in[6];
    const int*   ntypes = (const int*)d_in[7];
    const int*   tptr   = (const int*)d_in[8];

    float* hy  = (float*)d_out;
    float* cy  = hy + (size_t)B * NN * HH;
    float* gxo = cy + (size_t)B * NN * HH;

    cudaFuncSetAttribute(gates_gemm, cudaFuncAttributeMaxDynamicSharedMemorySize, SM_BYTES);

    // tf32 pre-conversion (device-symbol targets)
    float *p_wih, *p_whh, *p_in, *p_hx;
    cudaGetSymbolAddress((void**)&p_wih, g_wih_t);
    cudaGetSymbolAddress((void**)&p_whh, g_whh_t);
    cudaGetSymbolAddress((void**)&p_in,  g_in_t);
    cudaGetSymbolAddress((void**)&p_hx,  g_hx_t);

    {
        int n4;
        n4 = 5 * FH * II / 4;
        cvt_kernel<<<(n4 + 255) / 256, 256>>>((const float4*)wih, (float4*)p_wih, n4);
        n4 = 5 * FH * HH / 4;
        cvt_kernel<<<(n4 + 255) / 256, 256>>>((const float4*)whh, (float4*)p_whh, n4);
        n4 = B * NN * II / 4;
        cvt_kernel<<<(n4 + 255) / 256, 256>>>((const float4*)input, (float4*)p_in, n4);
        n4 = B * NN * HH / 4;
        cvt_kernel<<<(n4 + 255) / 256, 256>>>((const float4*)hx, (float4*)p_hx, n4);
    }

    gx_kernel<<<1, 512>>>(G, gxo);

    dim3 grid1(FH / TN, B / TM, NN);   // (16, 4, 21)
    gates_gemm<<<grid1, 256, SM_BYTES>>>(bhh, ntypes);

    dim3 grid2(HH / 128, B);           // (8, 512)
    pass2<<<grid2, 128>>>(cx, tptr, hy, cy);
}

// round 5
// speedup vs baseline: 4.3913x; 1.4487x over previous
#include <cuda_runtime.h>
#include <cuda_fp16.h>
#include <cstdint>

// ---------------- problem constants ----------------
#define B   512
#define NN  21
#define II  256
#define HH  1024
#define FH  4096          // 4*HH
#define KK  1280          // II + HH
#define EPS 1e-12f

// ---------------- GEMM tiling ----------------
#define TM 128            // batch rows per CTA
#define TN 256            // out cols per CTA
#define TK 32             // K halves per stage (64 bytes)
#define NSTAGE 4
#define NCHUNK (KK / TK)  // 40
#define PADB 80           // bytes per smem row (64 + 16 pad -> conflict-free ldmatrix)

#define A_STAGE_B (TM * PADB)      // 10240 bytes
#define B_STAGE_B (TN * PADB)      // 20480 bytes
#define STAGE_B   (A_STAGE_B + B_STAGE_B)
#define SM_BYTES  (NSTAGE * STAGE_B)   // 122880

// ---------------- scratch (__device__ globals; no allocation) ----------------
__device__ float  g_gates[(size_t)B * NN * FH];    // [B][NN][4H] pre-mix gates
__device__ float  g_gx[NN * NN];                   // row-L1-normalized G
__device__ __half g_wih_h[(size_t)5 * FH * II];    // fp16 weights
__device__ __half g_whh_h[(size_t)5 * FH * HH];
__device__ __half g_in_h[(size_t)B * NN * II];     // fp16 input
__device__ __half g_hx_h[(size_t)B * NN * HH];     // fp16 hx

// ---------------- helpers ----------------
__device__ __forceinline__ uint32_t smem_u32(const void* p) {
    uint32_t a;
    asm("{ .reg .u64 t; cvta.to.shared.u64 t, %1; cvt.u32.u64 %0, t; }" : "=r"(a) : "l"(p));
    return a;
}
__device__ __forceinline__ void cp16(uint32_t saddr, const void* gptr) {
    asm volatile("cp.async.cg.shared.global [%0], [%1], 16;" :: "r"(saddr), "l"(gptr));
}
__device__ __forceinline__ void ldsm4(uint32_t* r, uint32_t saddr) {
    asm volatile("ldmatrix.sync.aligned.m8n8.x4.shared.b16 {%0,%1,%2,%3}, [%4];"
                 : "=r"(r[0]), "=r"(r[1]), "=r"(r[2]), "=r"(r[3]) : "r"(saddr));
}
__device__ __forceinline__ void mma16(float* c, const uint32_t* a, const uint32_t* b) {
    asm volatile(
        "mma.sync.aligned.m16n8k16.row.col.f32.f16.f16.f32 "
        "{%0,%1,%2,%3}, {%4,%5,%6,%7}, {%8,%9}, {%0,%1,%2,%3};"
        : "+f"(c[0]), "+f"(c[1]), "+f"(c[2]), "+f"(c[3])
        : "r"(a[0]), "r"(a[1]), "r"(a[2]), "r"(a[3]), "r"(b[0]), "r"(b[1]));
}

// ---------------- kernel: fp32 -> fp16 conversion (8 elems/thread) ----------------
__global__ void cvt_h_kernel(const float4* __restrict__ src, uint4* __restrict__ dst, int n8) {
    int i = blockIdx.x * blockDim.x + threadIdx.x;
    if (i < n8) {
        float4 v0 = src[2 * i];
        float4 v1 = src[2 * i + 1];
        __half2 h0 = __floats2half2_rn(v0.x, v0.y);
        __half2 h1 = __floats2half2_rn(v0.z, v0.w);
        __half2 h2 = __floats2half2_rn(v1.x, v1.y);
        __half2 h3 = __floats2half2_rn(v1.z, v1.w);
        uint4 o;
        o.x = *(uint32_t*)&h0; o.y = *(uint32_t*)&h1;
        o.z = *(uint32_t*)&h2; o.w = *(uint32_t*)&h3;
        dst[i] = o;
    }
}

// ---------------- kernel 0: gx normalization ----------------
__global__ void gx_kernel(const float* __restrict__ G, float* __restrict__ gx_out) {
    __shared__ float sG[NN * NN];
    __shared__ float den[NN];
    __shared__ float den2[NN];
    int tid = threadIdx.x;
    for (int i = tid; i < NN * NN; i += blockDim.x) sG[i] = G[i];
    __syncthreads();
    if (tid < NN) {
        float s = 0.f;
        for (int j = 0; j < NN; j++) s += fabsf(sG[tid * NN + j]);
        den[tid] = fmaxf(s, EPS);
    }
    __syncthreads();
    for (int i = tid; i < NN * NN; i += blockDim.x) sG[i] = sG[i] / den[i / NN];
    __syncthreads();
    if (tid < NN) {
        float s = 0.f;
        for (int j = 0; j < NN; j++) s += fabsf(sG[tid * NN + j]);
        den2[tid] = fmaxf(s, EPS);
    }
    __syncthreads();
    for (int i = tid; i < NN * NN; i += blockDim.x) {
        g_gx[i]   = sG[i];
        gx_out[i] = sG[i] / den2[i / NN];
    }
}

// ---------------- kernel 1: fp16 mma.sync gates GEMM ----------------
// g_gates[b][n][o] = [input|hx] @ [Wih|Whh]^T + bias   (fp16 inputs, fp32 accum)
__global__ __launch_bounds__(256, 1)
void gates_gemm(const float* __restrict__ bhh, const int* __restrict__ ntypes) {
    extern __shared__ char smc[];
    const int tid  = threadIdx.x;
    const int lane = tid & 31;
    const int wid  = tid >> 5;

    const int n  = blockIdx.z;
    const int bm = blockIdx.y * TM;
    const int bo = blockIdx.x * TN;
    const int nt = ntypes[n];
    const __half* wih = g_wih_h + (size_t)nt * FH * II;
    const __half* whh = g_whh_h + (size_t)nt * FH * HH;

    const uint32_t sb = smem_u32(smc);

    // warp tiling: 2 (m) x 4 (n), warp tile 64x64
    const int wm = (wid & 1) * 64;
    const int wn = (wid >> 1) * 64;

    // ldmatrix lane roles (byte offsets within a 16-row x 32-byte k-slab)
    // A x4: m0=rows0-7 k0-7, m1=rows8-15 k0-7, m2=rows0-7 k8-15, m3=rows8-15 k8-15
    const uint32_t aL = (uint32_t)((((lane >> 3) & 1) * 8 + (lane & 7)) * PADB + (lane >> 4) * 16);
    // B x4: m0=n0-7 k0-7, m1=n0-7 k8-15, m2=n8-15 k0-7, m3=n8-15 k8-15
    const uint32_t bL = (uint32_t)((((lane >> 4) & 1) * 8 + (lane & 7)) * PADB + ((lane >> 3) & 1) * 16);

    float acc[4][8][4];
#pragma unroll
    for (int i = 0; i < 4; i++)
#pragma unroll
        for (int j = 0; j < 8; j++)
#pragma unroll
            for (int v = 0; v < 4; v++) acc[i][j][v] = 0.f;

    // ---- stage loader: A 512 chunks, B 1024 chunks of 16B ----
    auto load_stage = [&](int kt) {
        const int s  = kt % NSTAGE;
        const int k0 = kt * TK;                 // in halves
        const uint32_t ab = sb + (uint32_t)(s * STAGE_B);
        const uint32_t bb = ab + (uint32_t)A_STAGE_B;
#pragma unroll
        for (int i = 0; i < 2; i++) {
            int f = tid + i * 256;
            int r = f >> 2, c = f & 3;
            int k = k0 + c * 8;
            const __half* src = (k < II)
                ? g_in_h + ((size_t)(bm + r) * NN + n) * II + k
                : g_hx_h + ((size_t)(bm + r) * NN + n) * HH + (k - II);
            cp16(ab + (uint32_t)(r * PADB + c * 16), src);
        }
#pragma unroll
        for (int i = 0; i < 4; i++) {
            int f = tid + i * 256;
            int r = f >> 2, c = f & 3;
            int k = k0 + c * 8;
            const __half* src = (k < II)
                ? wih + (size_t)(bo + r) * II + k
                : whh + (size_t)(bo + r) * HH + (k - II);
            cp16(bb + (uint32_t)(r * PADB + c * 16), src);
        }
    };

    // prologue
#pragma unroll
    for (int s = 0; s < NSTAGE; s++) {
        load_stage(s);
        asm volatile("cp.async.commit_group;" ::: "memory");
    }

    // mainloop
    for (int kt = 0; kt < NCHUNK; kt++) {
        asm volatile("cp.async.wait_group %0;" :: "n"(NSTAGE - 1) : "memory");
        __syncthreads();

        const int s = kt % NSTAGE;
        const uint32_t sAb = sb + (uint32_t)(s * STAGE_B);
        const uint32_t sBb = sAb + (uint32_t)A_STAGE_B;

#pragma unroll
        for (int ks = 0; ks < TK / 16; ks++) {
            const uint32_t kb = (uint32_t)(ks * 32);   // 16 halves = 32 bytes
            uint32_t af[4][4];
#pragma unroll
            for (int mi = 0; mi < 4; mi++)
                ldsm4(af[mi], sAb + (uint32_t)((wm + mi * 16) * PADB) + kb + aL);
            uint32_t bq[4][4];
#pragma unroll
            for (int np = 0; np < 4; np++)
                ldsm4(bq[np], sBb + (uint32_t)((wn + np * 16) * PADB) + kb + bL);
#pragma unroll
            for (int mi = 0; mi < 4; mi++)
#pragma unroll
                for (int ni = 0; ni < 8; ni++)
                    mma16(acc[mi][ni], af[mi], &bq[ni >> 1][(ni & 1) * 2]);
        }
        __syncthreads();
        if (kt + NSTAGE < NCHUNK) load_stage(kt + NSTAGE);
        asm volatile("cp.async.commit_group;" ::: "memory");
    }

    // ---- epilogue: bias + store (mapping validated in rounds 3-4) ----
    const int lr = lane >> 2;
    const int lq = lane & 3;
    const float* brow = bhh + (size_t)nt * FH + bo;
#pragma unroll
    for (int mi = 0; mi < 4; mi++) {
        int r0 = wm + mi * 16 + lr;
        float* out0 = g_gates + ((size_t)(bm + r0)     * NN + n) * FH + bo;
        float* out1 = g_gates + ((size_t)(bm + r0 + 8) * NN + n) * FH + bo;
#pragma unroll
        for (int ni = 0; ni < 8; ni++) {
            int col = wn + ni * 8 + lq * 2;
            float2 bv = *(const float2*)(brow + col);
            float2 v0 = make_float2(acc[mi][ni][0] + bv.x, acc[mi][ni][1] + bv.y);
            float2 v1 = make_float2(acc[mi][ni][2] + bv.x, acc[mi][ni][3] + bv.y);
            *(float2*)(out0 + col) = v0;
            *(float2*)(out1 + col) = v1;
        }
    }
}

// ---------------- kernel 2: graph mix over n + LSTM epilogue ----------------
__global__ __launch_bounds__(128)
void pass2(const float* __restrict__ cx, const int* __restrict__ tptr,
           float* __restrict__ hy, float* __restrict__ cyo) {
    __shared__ float sgx[NN * NN];
    const int tid = threadIdx.x;
    for (int i = tid; i < NN * NN; i += 128) sgx[i] = g_gx[i];
    __syncthreads();

    const int b = blockIdx.y;
    const int h = blockIdx.x * 128 + tid;

    const float t1    = (float)(*tptr) + 1.0f;
    const float phase = floorf((float)h / (float)(HH - 1) * 8.0f + 1.0f);
    const float mask  = (fmodf(t1, phase) < 0.01f) ? 1.0f : 0.0f;

    float rg0[NN], rg1[NN], rg2[NN], rg3[NN];
    const float* gbase = g_gates + (size_t)b * NN * FH + h;
#pragma unroll
    for (int nI = 0; nI < NN; nI++) {
        rg0[nI] = gbase[(size_t)nI * FH];
        rg1[nI] = gbase[(size_t)nI * FH + HH];
        rg2[nI] = gbase[(size_t)nI * FH + 2 * HH];
        rg3[nI] = gbase[(size_t)nI * FH + 3 * HH];
    }

#pragma unroll 1
    for (int m = 0; m < NN; m++) {
        float ig = 0.f, fg = 0.f, cg = 0.f, og = 0.f;
#pragma unroll
        for (int nI = 0; nI < NN; nI++) {
            float w = sgx[m * NN + nI];
            ig = fmaf(w, rg0[nI], ig);
            fg = fmaf(w, rg1[nI], fg);
            cg = fmaf(w, rg2[nI], cg);
            og = fmaf(w, rg3[nI], og);
        }
        float is = 1.f / (1.f + expf(-ig));
        float fs = 1.f / (1.f + expf(-fg));
        float ct = tanhf(cg);
        float os = 1.f / (1.f + expf(-og));

        size_t idx = ((size_t)b * NN + m) * HH + h;
        float cxv = cx[idx];
        float cyv = mask * (fs * cxv + is * ct) + (1.0f - mask) * cxv;
        float hyv = os * tanhf(cyv);
        hy[idx]  = hyv;
        cyo[idx] = cyv;
    }
}

// ---------------- launch ----------------
extern "C" void kernel_launch(void* const* d_in, const int* in_sizes, int n_in,
                              void* d_out, int out_size) {
    const float* input  = (const float*)d_in[0];
    const float* hx     = (const float*)d_in[1];
    const float* cx     = (const float*)d_in[2];
    const float* G      = (const float*)d_in[3];
    const float* wih    = (const float*)d_in[4];
    const float* whh    = (const float*)d_in[5];
    const float* bhh    = (const float*)d_in[6];
    const int*   ntypes = (const int*)d_in[7];
    const int*   tptr   = (const int*)d_in[8];

    float* hy  = (float*)d_out;
    float* cy  = hy + (size_t)B * NN * HH;
    float* gxo = cy + (size_t)B * NN * HH;

    cudaFuncSetAttribute(gates_gemm, cudaFuncAttributeMaxDynamicSharedMemorySize, SM_BYTES);

    void *p_wih, *p_whh, *p_in, *p_hx;
    cudaGetSymbolAddress(&p_wih, g_wih_h);
    cudaGetSymbolAddress(&p_whh, g_whh_h);
    cudaGetSymbolAddress(&p_in,  g_in_h);
    cudaGetSymbolAddress(&p_hx,  g_hx_h);

    {
        int n8;
        n8 = 5 * FH * II / 8;
        cvt_h_kernel<<<(n8 + 255) / 256, 256>>>((const float4*)wih, (uint4*)p_wih, n8);
        n8 = 5 * FH * HH / 8;
        cvt_h_kernel<<<(n8 + 255) / 256, 256>>>((const float4*)whh, (uint4*)p_whh, n8);
        n8 = B * NN * II / 8;
        cvt_h_kernel<<<(n8 + 255) / 256, 256>>>((const float4*)input, (uint4*)p_in, n8);
        n8 = B * NN * HH / 8;
        cvt_h_kernel<<<(n8 + 255) / 256, 256>>>((const float4*)hx, (uint4*)p_hx, n8);
    }

    gx_kernel<<<1, 512>>>(G, gxo);

    dim3 grid1(FH / TN, B / TM, NN);   // (16, 4, 21)
    gates_gemm<<<grid1, 256, SM_BYTES>>>(bhh, ntypes);

    dim3 grid2(HH / 128, B);           // (8, 512)
    pass2<<<grid2, 128>>>(cx, tptr, hy, cy);
}